// round 1
// baseline (speedup 1.0000x reference)
#include <cuda_runtime.h>
#include <math.h>

#define N_DST 50000
#define L_MAX 16
#define D 256
#define N_CLS 104
#define BM 64

// Scratch (allocation-free rule: __device__ globals)
__device__ __align__(16) float g_last[(size_t)N_DST * D];
__device__ __align__(16) float g_h0[(size_t)N_DST * D];
__device__ __align__(16) float g_h1[(size_t)N_DST * D];

// ---------------------------------------------------------------------------
// Kernel 1: mailbox gather. One warp per node.
// h0 = sum of emb[tok[0..deg-2]], last = emb[tok[deg-1]].
// Lane owns 8 contiguous floats of the 256-wide row (2 float4 loads/row).
// ---------------------------------------------------------------------------
__global__ void gather_kernel(const int* __restrict__ tokens,
                              const int* __restrict__ degrees,
                              const float* __restrict__ emb)
{
    int gw   = (blockIdx.x * blockDim.x + threadIdx.x) >> 5;
    int lane = threadIdx.x & 31;
    if (gw >= N_DST) return;

    int deg = degrees[gw];
    deg = max(1, min(deg, L_MAX));

    const int* tk = tokens + gw * L_MAX;
    int mytok = (lane < L_MAX) ? tk[lane] : 0;

    int base = lane * 8;
    float4 a0 = make_float4(0.f, 0.f, 0.f, 0.f), a1 = a0;

    for (int l = 0; l < deg - 1; ++l) {
        int tkn = __shfl_sync(0xffffffffu, mytok, l);
        const float4* e = (const float4*)(emb + (size_t)tkn * D + base);
        float4 v0 = e[0], v1 = e[1];
        a0.x += v0.x; a0.y += v0.y; a0.z += v0.z; a0.w += v0.w;
        a1.x += v1.x; a1.y += v1.y; a1.z += v1.z; a1.w += v1.w;
    }
    int tl = __shfl_sync(0xffffffffu, mytok, deg - 1);
    const float4* e = (const float4*)(emb + (size_t)tl * D + base);
    float4 l0 = e[0], l1 = e[1];

    float4* h0p = (float4*)(g_h0 + (size_t)gw * D + base);
    float4* lp  = (float4*)(g_last + (size_t)gw * D + base);
    h0p[0] = a0; h0p[1] = a1;
    lp[0]  = l0; lp[1]  = l1;
}

// ---------------------------------------------------------------------------
// Kernel 2: GRU cell. Block = 256 threads handles BM=64 nodes.
// X (last,h0) for 64 nodes resident in smem (128 KB). Dim chunks of 32 (tx),
// 8 nodes per thread (ty + 8i). 6 gate accumulators per (node,dim).
// W tile smem layout [gate][dim][k] padded to 36 -> conflict-free vector LDS.
// Per 4-k step: 22 LDS.128 (16 of them warp-broadcast) vs 192 FFMA => FMA-bound.
// ---------------------------------------------------------------------------
__global__ __launch_bounds__(256, 1) void gru_kernel(
    const float* __restrict__ W_ih, const float* __restrict__ W_hh,
    const float* __restrict__ b_ih, const float* __restrict__ b_hh)
{
    extern __shared__ float smem[];
    float* Xl = smem;               // [BM][D]
    float* Xh = smem + BM * D;      // [BM][D]
    float* Ws = smem + 2 * BM * D;  // [6][32][36]

    int t  = threadIdx.x;
    int n0 = blockIdx.x * BM;

    // Stage X: 2 * 64 * 256 floats, coalesced float4
    #pragma unroll
    for (int i = 0; i < 16; ++i) {
        int f   = t + i * 256;
        int row = f >> 6;
        int c4  = (f & 63) << 2;
        int n   = n0 + row;
        float4 v1, v2;
        if (n < N_DST) {
            v1 = *(const float4*)&g_last[(size_t)n * D + c4];
            v2 = *(const float4*)&g_h0[(size_t)n * D + c4];
        } else {
            v1 = make_float4(0.f, 0.f, 0.f, 0.f); v2 = v1;
        }
        *(float4*)&Xl[row * D + c4] = v1;
        *(float4*)&Xh[row * D + c4] = v2;
    }

    int tx = t & 31, ty = t >> 5;

    #pragma unroll 1
    for (int chunk = 0; chunk < 8; ++chunk) {
        int dim = chunk * 32 + tx;
        float acc[6][8];
        #pragma unroll
        for (int g = 0; g < 6; ++g)
            #pragma unroll
            for (int i = 0; i < 8; ++i) acc[g][i] = 0.f;

        #pragma unroll 1
        for (int kt = 0; kt < 8; ++kt) {
            __syncthreads();
            // Load W tile: 6 gate-groups x 32 dims x 32 k (coalesced global,
            // conflict-free smem writes via pad-36)
            #pragma unroll
            for (int i = 0; i < 24; ++i) {
                int idx = t + i * 256;
                int k   = idx & 31;
                int dd  = (idx >> 5) & 31;
                int g   = idx >> 10;
                const float* Wsrc = (g < 3) ? W_ih : W_hh;
                int gg = (g < 3) ? g : (g - 3);
                Ws[g * 1152 + dd * 36 + k] =
                    Wsrc[(gg * 256 + chunk * 32 + dd) * 256 + kt * 32 + k];
            }
            __syncthreads();

            #pragma unroll
            for (int k = 0; k < 32; k += 4) {
                float4 w0 = *(float4*)&Ws[0 * 1152 + tx * 36 + k];
                float4 w1 = *(float4*)&Ws[1 * 1152 + tx * 36 + k];
                float4 w2 = *(float4*)&Ws[2 * 1152 + tx * 36 + k];
                float4 w3 = *(float4*)&Ws[3 * 1152 + tx * 36 + k];
                float4 w4 = *(float4*)&Ws[4 * 1152 + tx * 36 + k];
                float4 w5 = *(float4*)&Ws[5 * 1152 + tx * 36 + k];
                #pragma unroll
                for (int i = 0; i < 8; ++i) {
                    int m = ty + i * 8;
                    float4 xl = *(float4*)&Xl[m * D + kt * 32 + k];
                    float4 xh = *(float4*)&Xh[m * D + kt * 32 + k];
#define GRU_FMA(C) \
    acc[0][i] += w0.C * xl.C; \
    acc[1][i] += w1.C * xl.C; \
    acc[2][i] += w2.C * xl.C; \
    acc[3][i] += w3.C * xh.C; \
    acc[4][i] += w4.C * xh.C; \
    acc[5][i] += w5.C * xh.C;
                    GRU_FMA(x) GRU_FMA(y) GRU_FMA(z) GRU_FMA(w)
#undef GRU_FMA
                }
            }
        }

        // Epilogue: gates -> h1
        float bir = b_ih[dim], biz = b_ih[256 + dim], bin_ = b_ih[512 + dim];
        float bhr = b_hh[dim], bhz = b_hh[256 + dim], bhn  = b_hh[512 + dim];
        #pragma unroll
        for (int i = 0; i < 8; ++i) {
            int m = ty + i * 8;
            int n = n0 + m;
            if (n < N_DST) {
                float xr = acc[0][i] + bir + acc[3][i] + bhr;
                float xz = acc[1][i] + biz + acc[4][i] + bhz;
                float r  = 1.f / (1.f + __expf(-xr));
                float z  = 1.f / (1.f + __expf(-xz));
                float xn = acc[2][i] + bin_ + r * (acc[5][i] + bhn);
                float nn = 2.f / (1.f + __expf(-2.f * xn)) - 1.f;  // tanh
                float h0v = Xh[m * D + dim];
                g_h1[(size_t)n * D + dim] = (1.f - z) * nn + z * h0v;
            }
        }
    }
}

// ---------------------------------------------------------------------------
// Kernel 3: LayerNorm + degree-1 bypass. One warp per node, in-place on g_h1.
// ---------------------------------------------------------------------------
__global__ void ln_kernel(const int* __restrict__ degrees,
                          const float* __restrict__ gamma,
                          const float* __restrict__ beta)
{
    int gw   = (blockIdx.x * blockDim.x + threadIdx.x) >> 5;
    int lane = threadIdx.x & 31;
    if (gw >= N_DST) return;

    int deg = degrees[gw];
    size_t rowo = (size_t)gw * D;
    int base = lane * 8;

    float4 a = *(float4*)&g_h1[rowo + base];
    float4 b = *(float4*)&g_h1[rowo + base + 4];
    float s = a.x + a.y + a.z + a.w + b.x + b.y + b.z + b.w;
    float q = a.x*a.x + a.y*a.y + a.z*a.z + a.w*a.w
            + b.x*b.x + b.y*b.y + b.z*b.z + b.w*b.w;
    #pragma unroll
    for (int o = 16; o > 0; o >>= 1) {
        s += __shfl_xor_sync(0xffffffffu, s, o);
        q += __shfl_xor_sync(0xffffffffu, q, o);
    }
    float mu  = s * (1.f / 256.f);
    float var = q * (1.f / 256.f) - mu * mu;
    float inv = rsqrtf(fmaxf(var, 0.f) + 1e-5f);

    float4 o0, o1;
    if (deg == 1) {
        o0 = *(float4*)&g_last[rowo + base];
        o1 = *(float4*)&g_last[rowo + base + 4];
    } else {
        float4 g0 = *(const float4*)&gamma[base];
        float4 g1 = *(const float4*)&gamma[base + 4];
        float4 e0 = *(const float4*)&beta[base];
        float4 e1 = *(const float4*)&beta[base + 4];
        o0.x = (a.x - mu) * inv * g0.x + e0.x;
        o0.y = (a.y - mu) * inv * g0.y + e0.y;
        o0.z = (a.z - mu) * inv * g0.z + e0.z;
        o0.w = (a.w - mu) * inv * g0.w + e0.w;
        o1.x = (b.x - mu) * inv * g1.x + e1.x;
        o1.y = (b.y - mu) * inv * g1.y + e1.y;
        o1.z = (b.z - mu) * inv * g1.z + e1.z;
        o1.w = (b.w - mu) * inv * g1.w + e1.w;
    }
    *(float4*)&g_h1[rowo + base]     = o0;
    *(float4*)&g_h1[rowo + base + 4] = o1;
}

// ---------------------------------------------------------------------------
// Kernel 4: FC head. fc_w staged in smem transposed-padded [104][260].
// Warp processes 4 nodes at once; lane owns classes {l, l+32, l+64, l+96}.
// Per 4-k step: 4 w LDS.128 + 4 uniform ft LDG.128 + 64 FFMA.
// ---------------------------------------------------------------------------
__global__ __launch_bounds__(256) void fc_kernel(
    const float* __restrict__ fc_w, const float* __restrict__ fc_b,
    float* __restrict__ out)
{
    extern __shared__ float ws[];   // [104][260]
    __shared__ float bs[N_CLS];
    int t = threadIdx.x;

    for (int idx = t; idx < N_CLS * D; idx += 256) {
        int c = idx >> 8, k = idx & 255;
        ws[c * 260 + k] = fc_w[idx];
    }
    if (t < N_CLS) bs[t] = fc_b[t];
    __syncthreads();

    int lane = t & 31, wid = t >> 5;
    int c0 = lane, c1 = lane + 32, c2 = lane + 64, c3 = lane + 96;
    bool has3 = (c3 < N_CLS);

    for (int nb = (blockIdx.x * 8 + wid) * 4; nb < N_DST; nb += gridDim.x * 32) {
        float acc[4][4];
        #pragma unroll
        for (int j = 0; j < 4; ++j)
            #pragma unroll
            for (int c = 0; c < 4; ++c) acc[j][c] = 0.f;

        #pragma unroll 4
        for (int k = 0; k < D; k += 4) {
            float4 w0 = *(float4*)&ws[c0 * 260 + k];
            float4 w1 = *(float4*)&ws[c1 * 260 + k];
            float4 w2 = *(float4*)&ws[c2 * 260 + k];
            float4 w3 = has3 ? *(float4*)&ws[c3 * 260 + k]
                             : make_float4(0.f, 0.f, 0.f, 0.f);
            #pragma unroll
            for (int j = 0; j < 4; ++j) {
                int n = nb + j; if (n >= N_DST) n = N_DST - 1;
                float4 f = *(const float4*)&g_h1[(size_t)n * D + k];
                acc[j][0] += w0.x*f.x; acc[j][0] += w0.y*f.y; acc[j][0] += w0.z*f.z; acc[j][0] += w0.w*f.w;
                acc[j][1] += w1.x*f.x; acc[j][1] += w1.y*f.y; acc[j][1] += w1.z*f.z; acc[j][1] += w1.w*f.w;
                acc[j][2] += w2.x*f.x; acc[j][2] += w2.y*f.y; acc[j][2] += w2.z*f.z; acc[j][2] += w2.w*f.w;
                acc[j][3] += w3.x*f.x; acc[j][3] += w3.y*f.y; acc[j][3] += w3.z*f.z; acc[j][3] += w3.w*f.w;
            }
        }
        #pragma unroll
        for (int j = 0; j < 4; ++j) {
            int n = nb + j;
            if (n < N_DST) {
                float* o = out + (size_t)n * N_CLS;
                o[c0] = acc[j][0] + bs[c0];
                o[c1] = acc[j][1] + bs[c1];
                o[c2] = acc[j][2] + bs[c2];
                if (has3) o[c3] = acc[j][3] + bs[c3];
            }
        }
    }
}

// ---------------------------------------------------------------------------
extern "C" void kernel_launch(void* const* d_in, const int* in_sizes, int n_in,
                              void* d_out, int out_size)
{
    const int*   tokens  = (const int*)  d_in[0];
    const int*   degrees = (const int*)  d_in[1];
    const float* emb     = (const float*)d_in[2];
    const float* W_ih    = (const float*)d_in[3];
    const float* W_hh    = (const float*)d_in[4];
    const float* b_ih    = (const float*)d_in[5];
    const float* b_hh    = (const float*)d_in[6];
    const float* gamma   = (const float*)d_in[7];
    const float* beta    = (const float*)d_in[8];
    const float* fc_w    = (const float*)d_in[9];
    const float* fc_b    = (const float*)d_in[10];
    float* out = (float*)d_out;

    int gru_smem = (2 * BM * D + 6 * 32 * 36) * (int)sizeof(float);   // 158720 B
    int fc_smem  = N_CLS * 260 * (int)sizeof(float);                  // 108160 B
    cudaFuncSetAttribute(gru_kernel, cudaFuncAttributeMaxDynamicSharedMemorySize, gru_smem);
    cudaFuncSetAttribute(fc_kernel,  cudaFuncAttributeMaxDynamicSharedMemorySize, fc_smem);

    gather_kernel<<<(N_DST + 7) / 8, 256>>>(tokens, degrees, emb);
    gru_kernel<<<(N_DST + BM - 1) / BM, 256, gru_smem>>>(W_ih, W_hh, b_ih, b_hh);
    ln_kernel<<<(N_DST + 7) / 8, 256>>>(degrees, gamma, beta);
    fc_kernel<<<296, 256, fc_smem>>>(fc_w, fc_b, out);
}

// round 4
// speedup vs baseline: 2.3837x; 2.3837x over previous
#include <cuda_runtime.h>
#include <cuda_bf16.h>
#include <cstdint>
#include <math.h>

#define N_DST 50000
#define L_MAX 16
#define D 256
#define N_CLS 104

// ---------------------------------------------------------------------------
// Scratch (allocation-free rule: __device__ globals)
// ---------------------------------------------------------------------------
__device__ __align__(16) float g_last[(size_t)N_DST * D];
__device__ __align__(16) float g_h0[(size_t)N_DST * D];
__device__ __align__(16) float g_h1[(size_t)N_DST * D];

// ---------------------------------------------------------------------------
// Helpers: mma.sync / ldmatrix (baseline PTX, works on sm_100 non-a target)
// ---------------------------------------------------------------------------
__device__ __forceinline__ uint32_t smem_u32(const void* p) {
    uint32_t a;
    asm("{ .reg .u64 t; cvta.to.shared.u64 t, %1; cvt.u32.u64 %0, t; }"
        : "=r"(a) : "l"(p));
    return a;
}
__device__ __forceinline__ void ldsm4(uint32_t* r, uint32_t addr) {
    asm volatile("ldmatrix.sync.aligned.m8n8.x4.shared.b16 {%0,%1,%2,%3}, [%4];"
                 : "=r"(r[0]), "=r"(r[1]), "=r"(r[2]), "=r"(r[3]) : "r"(addr));
}
__device__ __forceinline__ void ldsm2(uint32_t* r, uint32_t addr) {
    asm volatile("ldmatrix.sync.aligned.m8n8.x2.shared.b16 {%0,%1}, [%2];"
                 : "=r"(r[0]), "=r"(r[1]) : "r"(addr));
}
__device__ __forceinline__ void mma16816(float* acc, const uint32_t* a, const uint32_t* b) {
    asm volatile("mma.sync.aligned.m16n8k16.row.col.f32.bf16.bf16.f32 "
                 "{%0,%1,%2,%3}, {%4,%5,%6,%7}, {%8,%9}, {%0,%1,%2,%3};"
                 : "+f"(acc[0]), "+f"(acc[1]), "+f"(acc[2]), "+f"(acc[3])
                 : "r"(a[0]), "r"(a[1]), "r"(a[2]), "r"(a[3]),
                   "r"(b[0]), "r"(b[1]));
}
// pack two floats as bf16x2 (a -> low 16 bits, b -> high 16 bits), RN
__device__ __forceinline__ uint32_t pack_bf16(float a, float b) {
    uint32_t r;
    asm("cvt.rn.bf16x2.f32 %0, %1, %2;" : "=r"(r) : "f"(b), "f"(a));
    return r;
}
__device__ __forceinline__ float lowf(uint32_t p) {
    __nv_bfloat162 v = *(__nv_bfloat162*)&p; return __bfloat162float(v.x);
}
__device__ __forceinline__ float highf(uint32_t p) {
    __nv_bfloat162 v = *(__nv_bfloat162*)&p; return __bfloat162float(v.y);
}
// split float4 -> two uint2 (hi pair-packed, lo pair-packed)
__device__ __forceinline__ void split4(float4 v, uint2& hi, uint2& lo) {
    uint32_t h0 = pack_bf16(v.x, v.y);
    uint32_t h1 = pack_bf16(v.z, v.w);
    uint32_t l0 = pack_bf16(v.x - lowf(h0), v.y - highf(h0));
    uint32_t l1 = pack_bf16(v.z - lowf(h1), v.w - highf(h1));
    hi = make_uint2(h0, h1);
    lo = make_uint2(l0, l1);
}
__device__ __forceinline__ float sigm(float x)   { return 1.f / (1.f + __expf(-x)); }
__device__ __forceinline__ float tanh_f(float x) { return 2.f / (1.f + __expf(-2.f * x)) - 1.f; }

// ---------------------------------------------------------------------------
// Kernel 1: mailbox gather. One warp per node.
// ---------------------------------------------------------------------------
__global__ void gather_kernel(const int* __restrict__ tokens,
                              const int* __restrict__ degrees,
                              const float* __restrict__ emb)
{
    int gw   = (blockIdx.x * blockDim.x + threadIdx.x) >> 5;
    int lane = threadIdx.x & 31;
    if (gw >= N_DST) return;

    int deg = degrees[gw];
    deg = max(1, min(deg, L_MAX));

    const int* tk = tokens + gw * L_MAX;
    int mytok = (lane < L_MAX) ? tk[lane] : 0;

    int base = lane * 8;
    float4 a0 = make_float4(0.f, 0.f, 0.f, 0.f), a1 = a0;

    for (int l = 0; l < deg - 1; ++l) {
        int tkn = __shfl_sync(0xffffffffu, mytok, l);
        const float4* e = (const float4*)(emb + (size_t)tkn * D + base);
        float4 v0 = e[0], v1 = e[1];
        a0.x += v0.x; a0.y += v0.y; a0.z += v0.z; a0.w += v0.w;
        a1.x += v1.x; a1.y += v1.y; a1.z += v1.z; a1.w += v1.w;
    }
    int tl = __shfl_sync(0xffffffffu, mytok, deg - 1);
    const float4* e = (const float4*)(emb + (size_t)tl * D + base);
    float4 l0 = e[0], l1 = e[1];

    float4* h0p = (float4*)(g_h0 + (size_t)gw * D + base);
    float4* lp  = (float4*)(g_last + (size_t)gw * D + base);
    h0p[0] = a0; h0p[1] = a1;
    lp[0]  = l0; lp[1]  = l1;
}

// ---------------------------------------------------------------------------
// Kernel 2: fused GRU via bf16-split mma.sync.
// Grid (8, 391): x = 32-dim chunk, y = 128-node tile. Consecutive blockIdx
// share the node tile -> co-resident -> A rows (last/h0) hit L2 7/8 times.
// C tile 128 x 192. B smem rows permuted per 16-dim slice s (0/1):
//   row = s*96 + gate*16 + dd, gate 0..2 = W_ih{r,z,n}, 3..5 = W_hh{r,z,n}.
// Warp grid 4M x 2N: warp (warp_m, warp_n=s) owns 32 rows x 96 cols = all six
// gates for its 16 dims -> fully register-local GRU epilogue.
// A operand: cols with gate<3 use 'last', gate>=3 use 'h0'.
// K = 256 in 8 chunks of 32; reg-prefetch pipelined single smem buffer.
// Smem bf16 tiles padded to 40 halves/row (80 B) -> conflict-free ldmatrix.
// ---------------------------------------------------------------------------
#define SM_A_LH 0
#define SM_A_LL 10240
#define SM_A_HH 20480
#define SM_A_HL 30720
#define SM_B_H  40960
#define SM_B_L  56320
#define G_SMEM  71680

__global__ __launch_bounds__(256, 1) void gru_mma_kernel(
    const float* __restrict__ Wih, const float* __restrict__ Whh,
    const float* __restrict__ bih, const float* __restrict__ bhh)
{
    extern __shared__ char sm[];
    uint32_t sb = smem_u32(sm);
    int t = threadIdx.x, lane = t & 31, wid = t >> 5;
    int warp_m = wid & 3, warp_n = wid >> 2;
    int n0 = blockIdx.y * 128;
    int d0 = blockIdx.x * 32;

    float acc[2][12][4];
    #pragma unroll
    for (int a = 0; a < 2; ++a)
        #pragma unroll
        for (int b = 0; b < 12; ++b)
            #pragma unroll
            for (int c = 0; c < 4; ++c) acc[a][b][c] = 0.f;

    // per-lane ldmatrix offsets
    int alr = ((lane >> 3) & 1) * 8 + (lane & 7);   // row within 16
    int alk = ((lane >> 4) & 1) * 8;                // k-half
    uint32_t aoff = (uint32_t)((warp_m * 32 + alr) * 80 + alk * 2);
    int l2 = lane & 15;
    uint32_t boff = (uint32_t)((warp_n * 96 + (l2 & 7)) * 80 + ((l2 >> 3) * 8) * 2);

    // prefetch registers
    float4 pa[8], pb[6];

    // ---- load chunk 0 ----
    {
        int kb = 0;
        #pragma unroll
        for (int i = 0; i < 8; ++i) {
            int idx = t + i * 256;
            int mat = idx >> 10, rem = idx & 1023;
            int row = rem >> 3, c4 = (rem & 7) << 2;
            int n = min(n0 + row, N_DST - 1);
            const float* src = mat ? g_h0 : g_last;
            pa[i] = *(const float4*)&src[(size_t)n * D + kb + c4];
        }
        #pragma unroll
        for (int i = 0; i < 6; ++i) {
            int idx = t + i * 256;
            int rB = idx >> 3, c4 = (idx & 7) << 2;
            int s = rB / 96, rem = rB % 96;
            int g = rem >> 4, dd = rem & 15;
            int dim = d0 + s * 16 + dd;
            const float* Wp = (g < 3) ? Wih : Whh;
            int gg = (g < 3) ? g : g - 3;
            pb[i] = *(const float4*)&Wp[(size_t)(gg * 256 + dim) * D + kb + c4];
        }
    }

    for (int kc = 0; kc < 8; ++kc) {
        // ---- store prefetched chunk to smem (bf16 split) ----
        #pragma unroll
        for (int i = 0; i < 8; ++i) {
            int idx = t + i * 256;
            int mat = idx >> 10, rem = idx & 1023;
            int row = rem >> 3, c4 = (rem & 7) << 2;
            uint2 hi, lo; split4(pa[i], hi, lo);
            uint32_t off = (uint32_t)(row * 80 + c4 * 2);
            if (mat == 0) {
                *(uint2*)(sm + SM_A_LH + off) = hi;
                *(uint2*)(sm + SM_A_LL + off) = lo;
            } else {
                *(uint2*)(sm + SM_A_HH + off) = hi;
                *(uint2*)(sm + SM_A_HL + off) = lo;
            }
        }
        #pragma unroll
        for (int i = 0; i < 6; ++i) {
            int idx = t + i * 256;
            int rB = idx >> 3, c4 = (idx & 7) << 2;
            uint2 hi, lo; split4(pb[i], hi, lo);
            uint32_t off = (uint32_t)(rB * 80 + c4 * 2);
            *(uint2*)(sm + SM_B_H + off) = hi;
            *(uint2*)(sm + SM_B_L + off) = lo;
        }
        __syncthreads();

        // ---- prefetch next chunk while mma runs ----
        if (kc < 7) {
            int kb = (kc + 1) * 32;
            #pragma unroll
            for (int i = 0; i < 8; ++i) {
                int idx = t + i * 256;
                int mat = idx >> 10, rem = idx & 1023;
                int row = rem >> 3, c4 = (rem & 7) << 2;
                int n = min(n0 + row, N_DST - 1);
                const float* src = mat ? g_h0 : g_last;
                pa[i] = *(const float4*)&src[(size_t)n * D + kb + c4];
            }
            #pragma unroll
            for (int i = 0; i < 6; ++i) {
                int idx = t + i * 256;
                int rB = idx >> 3, c4 = (idx & 7) << 2;
                int s = rB / 96, rem = rB % 96;
                int g = rem >> 4, dd = rem & 15;
                int dim = d0 + s * 16 + dd;
                const float* Wp = (g < 3) ? Wih : Whh;
                int gg = (g < 3) ? g : g - 3;
                pb[i] = *(const float4*)&Wp[(size_t)(gg * 256 + dim) * D + kb + c4];
            }
        }

        // ---- mma over this chunk ----
        #pragma unroll
        for (int ks = 0; ks < 2; ++ks) {
            uint32_t aLH[2][4], aLL[2][4], aHH[2][4], aHL[2][4];
            #pragma unroll
            for (int mt = 0; mt < 2; ++mt) {
                uint32_t o = aoff + (uint32_t)(mt * 1280 + ks * 32);
                ldsm4(aLH[mt], sb + SM_A_LH + o);
                ldsm4(aLL[mt], sb + SM_A_LL + o);
                ldsm4(aHH[mt], sb + SM_A_HH + o);
                ldsm4(aHL[mt], sb + SM_A_HL + o);
            }
            #pragma unroll
            for (int t8 = 0; t8 < 12; ++t8) {
                uint32_t bh[2], bl[2];
                uint32_t o = boff + (uint32_t)(t8 * 640 + ks * 32);
                ldsm2(bh, sb + SM_B_H + o);
                ldsm2(bl, sb + SM_B_L + o);
                bool useL = (t8 < 6);
                #pragma unroll
                for (int mt = 0; mt < 2; ++mt) {
                    const uint32_t* ah = useL ? aLH[mt] : aHH[mt];
                    const uint32_t* al = useL ? aLL[mt] : aHL[mt];
                    mma16816(acc[mt][t8], ah, bh);
                    mma16816(acc[mt][t8], ah, bl);
                    mma16816(acc[mt][t8], al, bh);
                }
            }
        }
        __syncthreads();
    }

    // ---- epilogue: all 6 gates register-local ----
    int lane4 = lane >> 2, lc = lane & 3;
    #pragma unroll
    for (int jh = 0; jh < 2; ++jh) {
        int dim = d0 + warp_n * 16 + jh * 8 + lc * 2;
        float2 birv = *(const float2*)&bih[dim];
        float2 bizv = *(const float2*)&bih[256 + dim];
        float2 binv = *(const float2*)&bih[512 + dim];
        float2 bhrv = *(const float2*)&bhh[dim];
        float2 bhzv = *(const float2*)&bhh[256 + dim];
        float2 bhnv = *(const float2*)&bhh[512 + dim];
        #pragma unroll
        for (int mt = 0; mt < 2; ++mt) {
            #pragma unroll
            for (int rs = 0; rs < 2; ++rs) {
                int m = n0 + warp_m * 32 + mt * 16 + rs * 8 + lane4;
                if (m < N_DST) {
                    float2 h0v = *(const float2*)&g_h0[(size_t)m * D + dim];
                    float o[2];
                    #pragma unroll
                    for (int e = 0; e < 2; ++e) {
                        int ci = rs * 2 + e;
                        float ir = acc[mt][0 + jh][ci]  + (e ? birv.y : birv.x);
                        float iz = acc[mt][2 + jh][ci]  + (e ? bizv.y : bizv.x);
                        float in_ = acc[mt][4 + jh][ci] + (e ? binv.y : binv.x);
                        float hr = acc[mt][6 + jh][ci]  + (e ? bhrv.y : bhrv.x);
                        float hz = acc[mt][8 + jh][ci]  + (e ? bhzv.y : bhzv.x);
                        float hn = acc[mt][10 + jh][ci] + (e ? bhnv.y : bhnv.x);
                        float r = sigm(ir + hr);
                        float z = sigm(iz + hz);
                        float nn = tanh_f(in_ + r * hn);
                        float h0e = e ? h0v.y : h0v.x;
                        o[e] = (1.f - z) * nn + z * h0e;
                    }
                    *(float2*)&g_h1[(size_t)m * D + dim] = make_float2(o[0], o[1]);
                }
            }
        }
    }
}

// ---------------------------------------------------------------------------
// Kernel 3: LayerNorm + degree-1 bypass. One warp per node, in-place on g_h1.
// ---------------------------------------------------------------------------
__global__ void ln_kernel(const int* __restrict__ degrees,
                          const float* __restrict__ gamma,
                          const float* __restrict__ beta)
{
    int gw   = (blockIdx.x * blockDim.x + threadIdx.x) >> 5;
    int lane = threadIdx.x & 31;
    if (gw >= N_DST) return;

    int deg = degrees[gw];
    size_t rowo = (size_t)gw * D;
    int base = lane * 8;

    float4 a = *(float4*)&g_h1[rowo + base];
    float4 b = *(float4*)&g_h1[rowo + base + 4];
    float s = a.x + a.y + a.z + a.w + b.x + b.y + b.z + b.w;
    float q = a.x*a.x + a.y*a.y + a.z*a.z + a.w*a.w
            + b.x*b.x + b.y*b.y + b.z*b.z + b.w*b.w;
    #pragma unroll
    for (int o = 16; o > 0; o >>= 1) {
        s += __shfl_xor_sync(0xffffffffu, s, o);
        q += __shfl_xor_sync(0xffffffffu, q, o);
    }
    float mu  = s * (1.f / 256.f);
    float var = q * (1.f / 256.f) - mu * mu;
    float inv = rsqrtf(fmaxf(var, 0.f) + 1e-5f);

    float4 o0, o1;
    if (deg == 1) {
        o0 = *(float4*)&g_last[rowo + base];
        o1 = *(float4*)&g_last[rowo + base + 4];
    } else {
        float4 g0 = *(const float4*)&gamma[base];
        float4 g1 = *(const float4*)&gamma[base + 4];
        float4 e0 = *(const float4*)&beta[base];
        float4 e1 = *(const float4*)&beta[base + 4];
        o0.x = (a.x - mu) * inv * g0.x + e0.x;
        o0.y = (a.y - mu) * inv * g0.y + e0.y;
        o0.z = (a.z - mu) * inv * g0.z + e0.z;
        o0.w = (a.w - mu) * inv * g0.w + e0.w;
        o1.x = (b.x - mu) * inv * g1.x + e1.x;
        o1.y = (b.y - mu) * inv * g1.y + e1.y;
        o1.z = (b.z - mu) * inv * g1.z + e1.z;
        o1.w = (b.w - mu) * inv * g1.w + e1.w;
    }
    *(float4*)&g_h1[rowo + base]     = o0;
    *(float4*)&g_h1[rowo + base + 4] = o1;
}

// ---------------------------------------------------------------------------
// Kernel 4: FC head via bf16-split mma.sync. C[50000,104] = ft @ fc_w^T + b.
// Grid 391, block 256. C tile 128 x 104 (13 n8 tiles; warp_n=0 -> 7, =1 -> 6).
// ---------------------------------------------------------------------------
#define F_A_H 0
#define F_A_L 10240
#define F_B_H 20480
#define F_B_L 28800
#define F_SMEM 37120

__global__ __launch_bounds__(256, 1) void fc_mma_kernel(
    const float* __restrict__ fcw, const float* __restrict__ fcb,
    float* __restrict__ out)
{
    extern __shared__ char sm[];
    uint32_t sb = smem_u32(sm);
    int t = threadIdx.x, lane = t & 31, wid = t >> 5;
    int warp_m = wid & 3, warp_n = wid >> 2;
    int n0 = blockIdx.x * 128;
    int nt = warp_n ? 6 : 7;
    int t8base = warp_n ? 7 : 0;

    float acc[2][7][4];
    #pragma unroll
    for (int a = 0; a < 2; ++a)
        #pragma unroll
        for (int b = 0; b < 7; ++b)
            #pragma unroll
            for (int c = 0; c < 4; ++c) acc[a][b][c] = 0.f;

    int alr = ((lane >> 3) & 1) * 8 + (lane & 7);
    int alk = ((lane >> 4) & 1) * 8;
    uint32_t aoff = (uint32_t)((warp_m * 32 + alr) * 80 + alk * 2);
    int l2 = lane & 15;
    uint32_t boff = (uint32_t)((t8base * 8 + (l2 & 7)) * 80 + ((l2 >> 3) * 8) * 2);

    float4 pa[4], pb[4];
    {
        int kb = 0;
        #pragma unroll
        for (int i = 0; i < 4; ++i) {
            int idx = t + i * 256;
            int row = idx >> 3, c4 = (idx & 7) << 2;
            int n = min(n0 + row, N_DST - 1);
            pa[i] = *(const float4*)&g_h1[(size_t)n * D + kb + c4];
        }
        #pragma unroll
        for (int i = 0; i < 4; ++i) {
            int idx = t + i * 256;
            if (idx < N_CLS * 8) {
                int row = idx >> 3, c4 = (idx & 7) << 2;
                pb[i] = *(const float4*)&fcw[(size_t)row * D + kb + c4];
            }
        }
    }

    for (int kc = 0; kc < 8; ++kc) {
        #pragma unroll
        for (int i = 0; i < 4; ++i) {
            int idx = t + i * 256;
            int row = idx >> 3, c4 = (idx & 7) << 2;
            uint2 hi, lo; split4(pa[i], hi, lo);
            uint32_t off = (uint32_t)(row * 80 + c4 * 2);
            *(uint2*)(sm + F_A_H + off) = hi;
            *(uint2*)(sm + F_A_L + off) = lo;
        }
        #pragma unroll
        for (int i = 0; i < 4; ++i) {
            int idx = t + i * 256;
            if (idx < N_CLS * 8) {
                int row = idx >> 3, c4 = (idx & 7) << 2;
                uint2 hi, lo; split4(pb[i], hi, lo);
                uint32_t off = (uint32_t)(row * 80 + c4 * 2);
                *(uint2*)(sm + F_B_H + off) = hi;
                *(uint2*)(sm + F_B_L + off) = lo;
            }
        }
        __syncthreads();

        if (kc < 7) {
            int kb = (kc + 1) * 32;
            #pragma unroll
            for (int i = 0; i < 4; ++i) {
                int idx = t + i * 256;
                int row = idx >> 3, c4 = (idx & 7) << 2;
                int n = min(n0 + row, N_DST - 1);
                pa[i] = *(const float4*)&g_h1[(size_t)n * D + kb + c4];
            }
            #pragma unroll
            for (int i = 0; i < 4; ++i) {
                int idx = t + i * 256;
                if (idx < N_CLS * 8) {
                    int row = idx >> 3, c4 = (idx & 7) << 2;
                    pb[i] = *(const float4*)&fcw[(size_t)row * D + kb + c4];
                }
            }
        }

        #pragma unroll
        for (int ks = 0; ks < 2; ++ks) {
            uint32_t aH[2][4], aL[2][4];
            #pragma unroll
            for (int mt = 0; mt < 2; ++mt) {
                uint32_t o = aoff + (uint32_t)(mt * 1280 + ks * 32);
                ldsm4(aH[mt], sb + F_A_H + o);
                ldsm4(aL[mt], sb + F_A_L + o);
            }
            #pragma unroll
            for (int t8 = 0; t8 < 7; ++t8) {
                if (t8 < nt) {
                    uint32_t bh[2], bl[2];
                    uint32_t o = boff + (uint32_t)(t8 * 640 + ks * 32);
                    ldsm2(bh, sb + F_B_H + o);
                    ldsm2(bl, sb + F_B_L + o);
                    #pragma unroll
                    for (int mt = 0; mt < 2; ++mt) {
                        mma16816(acc[mt][t8], aH[mt], bh);
                        mma16816(acc[mt][t8], aH[mt], bl);
                        mma16816(acc[mt][t8], aL[mt], bh);
                    }
                }
            }
        }
        __syncthreads();
    }

    // epilogue
    int lane4 = lane >> 2, lc = lane & 3;
    for (int t8 = 0; t8 < nt; ++t8) {
        int col = (t8base + t8) * 8 + lc * 2;
        float2 bv = *(const float2*)&fcb[col];
        #pragma unroll
        for (int mt = 0; mt < 2; ++mt) {
            #pragma unroll
            for (int rs = 0; rs < 2; ++rs) {
                int m = n0 + warp_m * 32 + mt * 16 + rs * 8 + lane4;
                if (m < N_DST) {
                    float2 o = make_float2(acc[mt][t8][rs * 2 + 0] + bv.x,
                                           acc[mt][t8][rs * 2 + 1] + bv.y);
                    *(float2*)&out[(size_t)m * N_CLS + col] = o;
                }
            }
        }
    }
}

// ---------------------------------------------------------------------------
extern "C" void kernel_launch(void* const* d_in, const int* in_sizes, int n_in,
                              void* d_out, int out_size)
{
    const int*   tokens  = (const int*)  d_in[0];
    const int*   degrees = (const int*)  d_in[1];
    const float* emb     = (const float*)d_in[2];
    const float* W_ih    = (const float*)d_in[3];
    const float* W_hh    = (const float*)d_in[4];
    const float* b_ih    = (const float*)d_in[5];
    const float* b_hh    = (const float*)d_in[6];
    const float* gamma   = (const float*)d_in[7];
    const float* beta    = (const float*)d_in[8];
    const float* fc_w    = (const float*)d_in[9];
    const float* fc_b    = (const float*)d_in[10];
    float* out = (float*)d_out;

    cudaFuncSetAttribute(gru_mma_kernel, cudaFuncAttributeMaxDynamicSharedMemorySize, G_SMEM);
    cudaFuncSetAttribute(fc_mma_kernel,  cudaFuncAttributeMaxDynamicSharedMemorySize, F_SMEM);

    gather_kernel<<<(N_DST + 7) / 8, 256>>>(tokens, degrees, emb);
    gru_mma_kernel<<<dim3(8, 391), 256, G_SMEM>>>(W_ih, W_hh, b_ih, b_hh);
    ln_kernel<<<(N_DST + 7) / 8, 256>>>(degrees, gamma, beta);
    fc_mma_kernel<<<391, 256, F_SMEM>>>(fc_w, fc_b, out);
}

// round 5
// speedup vs baseline: 2.4564x; 1.0305x over previous
#include <cuda_runtime.h>
#include <cuda_bf16.h>
#include <cstdint>
#include <math.h>

#define N_DST 50000
#define L_MAX 16
#define D 256
#define N_CLS 104

// ---------------------------------------------------------------------------
// Scratch (allocation-free rule: __device__ globals)
// ---------------------------------------------------------------------------
__device__ __align__(16) float g_last[(size_t)N_DST * D];
__device__ __align__(16) float g_h0[(size_t)N_DST * D];
__device__ __align__(16) float g_h1[(size_t)N_DST * D];

// ---------------------------------------------------------------------------
// Helpers: mma.sync / ldmatrix (baseline PTX, works on sm_100 non-a target)
// ---------------------------------------------------------------------------
__device__ __forceinline__ uint32_t smem_u32(const void* p) {
    uint32_t a;
    asm("{ .reg .u64 t; cvta.to.shared.u64 t, %1; cvt.u32.u64 %0, t; }"
        : "=r"(a) : "l"(p));
    return a;
}
__device__ __forceinline__ void ldsm4(uint32_t* r, uint32_t addr) {
    asm volatile("ldmatrix.sync.aligned.m8n8.x4.shared.b16 {%0,%1,%2,%3}, [%4];"
                 : "=r"(r[0]), "=r"(r[1]), "=r"(r[2]), "=r"(r[3]) : "r"(addr));
}
__device__ __forceinline__ void ldsm2(uint32_t* r, uint32_t addr) {
    asm volatile("ldmatrix.sync.aligned.m8n8.x2.shared.b16 {%0,%1}, [%2];"
                 : "=r"(r[0]), "=r"(r[1]) : "r"(addr));
}
__device__ __forceinline__ void mma16816(float* acc, const uint32_t* a, const uint32_t* b) {
    asm volatile("mma.sync.aligned.m16n8k16.row.col.f32.bf16.bf16.f32 "
                 "{%0,%1,%2,%3}, {%4,%5,%6,%7}, {%8,%9}, {%0,%1,%2,%3};"
                 : "+f"(acc[0]), "+f"(acc[1]), "+f"(acc[2]), "+f"(acc[3])
                 : "r"(a[0]), "r"(a[1]), "r"(a[2]), "r"(a[3]),
                   "r"(b[0]), "r"(b[1]));
}
// pack two floats as bf16x2 (a -> low 16 bits, b -> high 16 bits), RN
__device__ __forceinline__ uint32_t pack_bf16(float a, float b) {
    uint32_t r;
    asm("cvt.rn.bf16x2.f32 %0, %1, %2;" : "=r"(r) : "f"(b), "f"(a));
    return r;
}
__device__ __forceinline__ float lowf(uint32_t p) {
    __nv_bfloat162 v = *(__nv_bfloat162*)&p; return __bfloat162float(v.x);
}
__device__ __forceinline__ float highf(uint32_t p) {
    __nv_bfloat162 v = *(__nv_bfloat162*)&p; return __bfloat162float(v.y);
}
// split float4 -> two uint2 (hi pair-packed, lo pair-packed)
__device__ __forceinline__ void split4(float4 v, uint2& hi, uint2& lo) {
    uint32_t h0 = pack_bf16(v.x, v.y);
    uint32_t h1 = pack_bf16(v.z, v.w);
    uint32_t l0 = pack_bf16(v.x - lowf(h0), v.y - highf(h0));
    uint32_t l1 = pack_bf16(v.z - lowf(h1), v.w - highf(h1));
    hi = make_uint2(h0, h1);
    lo = make_uint2(l0, l1);
}
__device__ __forceinline__ float sigm(float x)   { return 1.f / (1.f + __expf(-x)); }
__device__ __forceinline__ float tanh_f(float x) { return 2.f / (1.f + __expf(-2.f * x)) - 1.f; }

// ---------------------------------------------------------------------------
// Kernel 1: mailbox gather. One warp per node.
// ---------------------------------------------------------------------------
__global__ void gather_kernel(const int* __restrict__ tokens,
                              const int* __restrict__ degrees,
                              const float* __restrict__ emb)
{
    int gw   = (blockIdx.x * blockDim.x + threadIdx.x) >> 5;
    int lane = threadIdx.x & 31;
    if (gw >= N_DST) return;

    int deg = degrees[gw];
    deg = max(1, min(deg, L_MAX));

    const int* tk = tokens + gw * L_MAX;
    int mytok = (lane < L_MAX) ? tk[lane] : 0;

    int base = lane * 8;
    float4 a0 = make_float4(0.f, 0.f, 0.f, 0.f), a1 = a0;

    for (int l = 0; l < deg - 1; ++l) {
        int tkn = __shfl_sync(0xffffffffu, mytok, l);
        const float4* e = (const float4*)(emb + (size_t)tkn * D + base);
        float4 v0 = e[0], v1 = e[1];
        a0.x += v0.x; a0.y += v0.y; a0.z += v0.z; a0.w += v0.w;
        a1.x += v1.x; a1.y += v1.y; a1.z += v1.z; a1.w += v1.w;
    }
    int tl = __shfl_sync(0xffffffffu, mytok, deg - 1);
    const float4* e = (const float4*)(emb + (size_t)tl * D + base);
    float4 l0 = e[0], l1 = e[1];

    float4* h0p = (float4*)(g_h0 + (size_t)gw * D + base);
    float4* lp  = (float4*)(g_last + (size_t)gw * D + base);
    h0p[0] = a0; h0p[1] = a1;
    lp[0]  = l0; lp[1]  = l1;
}

// ---------------------------------------------------------------------------
// Kernel 2: fused GRU via bf16-split mma.sync, double-buffered smem.
// Grid (8, 391): x = 32-dim chunk, y = 128-node tile (consecutive bids share
// the node tile -> A rows L2-hit 7/8 times).
// C tile 128 x 192; B rows permuted: row = s*96 + gate*16 + dd.
// Warp grid 4M x 2N; each warp holds all six gates for its 16 dims.
// K = 256 in 8 chunks of 32; ping-pong smem, 1 sync per chunk; B via ldsm4
// pairs (2 n8 tiles per ldmatrix).
// ---------------------------------------------------------------------------
#define SM_A_LH 0
#define SM_A_LL 10240
#define SM_A_HH 20480
#define SM_A_HL 30720
#define SM_B_H  40960
#define SM_B_L  56320
#define GB_STRIDE 71680
#define G_SMEM (2 * GB_STRIDE)

__device__ __forceinline__ void gru_load(float4* pa, float4* pb, int t, int n0,
                                         int d0, int kb,
                                         const float* __restrict__ Wih,
                                         const float* __restrict__ Whh)
{
    #pragma unroll
    for (int i = 0; i < 8; ++i) {
        int idx = t + i * 256;
        int mat = idx >> 10, rem = idx & 1023;
        int row = rem >> 3, c4 = (rem & 7) << 2;
        int n = min(n0 + row, N_DST - 1);
        const float* src = mat ? g_h0 : g_last;
        pa[i] = *(const float4*)&src[(size_t)n * D + kb + c4];
    }
    #pragma unroll
    for (int i = 0; i < 6; ++i) {
        int idx = t + i * 256;
        int rB = idx >> 3, c4 = (idx & 7) << 2;
        int s = rB / 96, rem = rB % 96;
        int g = rem >> 4, dd = rem & 15;
        int dim = d0 + s * 16 + dd;
        const float* Wp = (g < 3) ? Wih : Whh;
        int gg = (g < 3) ? g : g - 3;
        pb[i] = *(const float4*)&Wp[(size_t)(gg * 256 + dim) * D + kb + c4];
    }
}

__device__ __forceinline__ void gru_store(char* buf, const float4* pa,
                                          const float4* pb, int t)
{
    #pragma unroll
    for (int i = 0; i < 8; ++i) {
        int idx = t + i * 256;
        int mat = idx >> 10, rem = idx & 1023;
        int row = rem >> 3, c4 = (rem & 7) << 2;
        uint2 hi, lo; split4(pa[i], hi, lo);
        uint32_t off = (uint32_t)(row * 80 + c4 * 2);
        if (mat == 0) {
            *(uint2*)(buf + SM_A_LH + off) = hi;
            *(uint2*)(buf + SM_A_LL + off) = lo;
        } else {
            *(uint2*)(buf + SM_A_HH + off) = hi;
            *(uint2*)(buf + SM_A_HL + off) = lo;
        }
    }
    #pragma unroll
    for (int i = 0; i < 6; ++i) {
        int idx = t + i * 256;
        int rB = idx >> 3, c4 = (idx & 7) << 2;
        uint2 hi, lo; split4(pb[i], hi, lo);
        uint32_t off = (uint32_t)(rB * 80 + c4 * 2);
        *(uint2*)(buf + SM_B_H + off) = hi;
        *(uint2*)(buf + SM_B_L + off) = lo;
    }
}

__global__ __launch_bounds__(256, 1) void gru_mma_kernel(
    const float* __restrict__ Wih, const float* __restrict__ Whh,
    const float* __restrict__ bih, const float* __restrict__ bhh)
{
    extern __shared__ char sm[];
    uint32_t sb = smem_u32(sm);
    int t = threadIdx.x, lane = t & 31, wid = t >> 5;
    int warp_m = wid & 3, warp_n = wid >> 2;
    int n0 = blockIdx.y * 128;
    int d0 = blockIdx.x * 32;

    float acc[2][12][4];
    #pragma unroll
    for (int a = 0; a < 2; ++a)
        #pragma unroll
        for (int b = 0; b < 12; ++b)
            #pragma unroll
            for (int c = 0; c < 4; ++c) acc[a][b][c] = 0.f;

    // A ldsm4 lane offset
    int alr = ((lane >> 3) & 1) * 8 + (lane & 7);
    int alk = ((lane >> 4) & 1) * 8;
    uint32_t aoff = (uint32_t)((warp_m * 32 + alr) * 80 + alk * 2);
    // B ldsm4 pair lane offset: lanes 0-7 -> (t8p,k0), 8-15 -> (t8p,k1),
    // 16-23 -> (t8p+1,k0), 24-31 -> (t8p+1,k1)
    int bmx = lane >> 3, brow = lane & 7;
    uint32_t boff = (uint32_t)((warp_n * 96 + (bmx >> 1) * 8 + brow) * 80 +
                               (bmx & 1) * 16);

    float4 pa[8], pb[6];
    gru_load(pa, pb, t, n0, d0, 0, Wih, Whh);
    gru_store(sm, pa, pb, t);
    __syncthreads();

    for (int kc = 0; kc < 8; ++kc) {
        uint32_t sbc = sb + (uint32_t)((kc & 1) * GB_STRIDE);
        char* nxt = sm + ((kc & 1) ^ 1) * GB_STRIDE;
        if (kc < 7) gru_load(pa, pb, t, n0, d0, (kc + 1) * 32, Wih, Whh);

        #pragma unroll
        for (int ks = 0; ks < 2; ++ks) {
            uint32_t aLH[2][4], aLL[2][4], aHH[2][4], aHL[2][4];
            #pragma unroll
            for (int mt = 0; mt < 2; ++mt) {
                uint32_t o = aoff + (uint32_t)(mt * 1280 + ks * 32);
                ldsm4(aLH[mt], sbc + SM_A_LH + o);
                ldsm4(aLL[mt], sbc + SM_A_LL + o);
                ldsm4(aHH[mt], sbc + SM_A_HH + o);
                ldsm4(aHL[mt], sbc + SM_A_HL + o);
            }
            #pragma unroll
            for (int t8p = 0; t8p < 12; t8p += 2) {
                uint32_t bh4[4], bl4[4];
                uint32_t o = boff + (uint32_t)(t8p * 640 + ks * 32);
                ldsm4(bh4, sbc + SM_B_H + o);
                ldsm4(bl4, sbc + SM_B_L + o);
                bool useL = (t8p < 6);
                #pragma unroll
                for (int h = 0; h < 2; ++h) {
                    int t8 = t8p + h;
                    #pragma unroll
                    for (int mt = 0; mt < 2; ++mt) {
                        const uint32_t* ah = useL ? aLH[mt] : aHH[mt];
                        const uint32_t* al = useL ? aLL[mt] : aHL[mt];
                        mma16816(acc[mt][t8], ah, bh4 + 2 * h);
                        mma16816(acc[mt][t8], ah, bl4 + 2 * h);
                        mma16816(acc[mt][t8], al, bh4 + 2 * h);
                    }
                }
            }
        }
        if (kc < 7) gru_store(nxt, pa, pb, t);
        __syncthreads();
    }

    // ---- epilogue: all 6 gates register-local ----
    int lane4 = lane >> 2, lc = lane & 3;
    #pragma unroll
    for (int jh = 0; jh < 2; ++jh) {
        int dim = d0 + warp_n * 16 + jh * 8 + lc * 2;
        float2 birv = *(const float2*)&bih[dim];
        float2 bizv = *(const float2*)&bih[256 + dim];
        float2 binv = *(const float2*)&bih[512 + dim];
        float2 bhrv = *(const float2*)&bhh[dim];
        float2 bhzv = *(const float2*)&bhh[256 + dim];
        float2 bhnv = *(const float2*)&bhh[512 + dim];
        #pragma unroll
        for (int mt = 0; mt < 2; ++mt) {
            #pragma unroll
            for (int rs = 0; rs < 2; ++rs) {
                int m = n0 + warp_m * 32 + mt * 16 + rs * 8 + lane4;
                if (m < N_DST) {
                    float2 h0v = *(const float2*)&g_h0[(size_t)m * D + dim];
                    float o[2];
                    #pragma unroll
                    for (int e = 0; e < 2; ++e) {
                        int ci = rs * 2 + e;
                        float ir = acc[mt][0 + jh][ci]  + (e ? birv.y : birv.x);
                        float iz = acc[mt][2 + jh][ci]  + (e ? bizv.y : bizv.x);
                        float in_ = acc[mt][4 + jh][ci] + (e ? binv.y : binv.x);
                        float hr = acc[mt][6 + jh][ci]  + (e ? bhrv.y : bhrv.x);
                        float hz = acc[mt][8 + jh][ci]  + (e ? bhzv.y : bhzv.x);
                        float hn = acc[mt][10 + jh][ci] + (e ? bhnv.y : bhnv.x);
                        float r = sigm(ir + hr);
                        float z = sigm(iz + hz);
                        float nn = tanh_f(in_ + r * hn);
                        float h0e = e ? h0v.y : h0v.x;
                        o[e] = (1.f - z) * nn + z * h0e;
                    }
                    *(float2*)&g_h1[(size_t)m * D + dim] = make_float2(o[0], o[1]);
                }
            }
        }
    }
}

// ---------------------------------------------------------------------------
// Kernel 3: LayerNorm + degree-1 bypass. One warp per node, in-place on g_h1.
// ---------------------------------------------------------------------------
__global__ void ln_kernel(const int* __restrict__ degrees,
                          const float* __restrict__ gamma,
                          const float* __restrict__ beta)
{
    int gw   = (blockIdx.x * blockDim.x + threadIdx.x) >> 5;
    int lane = threadIdx.x & 31;
    if (gw >= N_DST) return;

    int deg = degrees[gw];
    size_t rowo = (size_t)gw * D;
    int base = lane * 8;

    float4 a = *(float4*)&g_h1[rowo + base];
    float4 b = *(float4*)&g_h1[rowo + base + 4];
    float s = a.x + a.y + a.z + a.w + b.x + b.y + b.z + b.w;
    float q = a.x*a.x + a.y*a.y + a.z*a.z + a.w*a.w
            + b.x*b.x + b.y*b.y + b.z*b.z + b.w*b.w;
    #pragma unroll
    for (int o = 16; o > 0; o >>= 1) {
        s += __shfl_xor_sync(0xffffffffu, s, o);
        q += __shfl_xor_sync(0xffffffffu, q, o);
    }
    float mu  = s * (1.f / 256.f);
    float var = q * (1.f / 256.f) - mu * mu;
    float inv = rsqrtf(fmaxf(var, 0.f) + 1e-5f);

    float4 o0, o1;
    if (deg == 1) {
        o0 = *(float4*)&g_last[rowo + base];
        o1 = *(float4*)&g_last[rowo + base + 4];
    } else {
        float4 g0 = *(const float4*)&gamma[base];
        float4 g1 = *(const float4*)&gamma[base + 4];
        float4 e0 = *(const float4*)&beta[base];
        float4 e1 = *(const float4*)&beta[base + 4];
        o0.x = (a.x - mu) * inv * g0.x + e0.x;
        o0.y = (a.y - mu) * inv * g0.y + e0.y;
        o0.z = (a.z - mu) * inv * g0.z + e0.z;
        o0.w = (a.w - mu) * inv * g0.w + e0.w;
        o1.x = (b.x - mu) * inv * g1.x + e1.x;
        o1.y = (b.y - mu) * inv * g1.y + e1.y;
        o1.z = (b.z - mu) * inv * g1.z + e1.z;
        o1.w = (b.w - mu) * inv * g1.w + e1.w;
    }
    *(float4*)&g_h1[rowo + base]     = o0;
    *(float4*)&g_h1[rowo + base + 4] = o1;
}

// ---------------------------------------------------------------------------
// Kernel 4: FC head via bf16-split mma.sync, double-buffered.
// Grid 391, block 256. C tile 128 x 104 (13 n8 tiles; warp_n=0 -> 7, =1 -> 6).
// ---------------------------------------------------------------------------
#define F_A_H 0
#define F_A_L 10240
#define F_B_H 20480
#define F_B_L 28800
#define FB_STRIDE 37120
#define F_SMEM (2 * FB_STRIDE)

__device__ __forceinline__ void fc_load(float4* pa, float4* pb, int t, int n0,
                                        int kb, const float* __restrict__ fcw)
{
    #pragma unroll
    for (int i = 0; i < 4; ++i) {
        int idx = t + i * 256;
        int row = idx >> 3, c4 = (idx & 7) << 2;
        int n = min(n0 + row, N_DST - 1);
        pa[i] = *(const float4*)&g_h1[(size_t)n * D + kb + c4];
    }
    #pragma unroll
    for (int i = 0; i < 4; ++i) {
        int idx = t + i * 256;
        if (idx < N_CLS * 8) {
            int row = idx >> 3, c4 = (idx & 7) << 2;
            pb[i] = *(const float4*)&fcw[(size_t)row * D + kb + c4];
        }
    }
}

__device__ __forceinline__ void fc_store(char* buf, const float4* pa,
                                         const float4* pb, int t)
{
    #pragma unroll
    for (int i = 0; i < 4; ++i) {
        int idx = t + i * 256;
        int row = idx >> 3, c4 = (idx & 7) << 2;
        uint2 hi, lo; split4(pa[i], hi, lo);
        uint32_t off = (uint32_t)(row * 80 + c4 * 2);
        *(uint2*)(buf + F_A_H + off) = hi;
        *(uint2*)(buf + F_A_L + off) = lo;
    }
    #pragma unroll
    for (int i = 0; i < 4; ++i) {
        int idx = t + i * 256;
        if (idx < N_CLS * 8) {
            int row = idx >> 3, c4 = (idx & 7) << 2;
            uint2 hi, lo; split4(pb[i], hi, lo);
            uint32_t off = (uint32_t)(row * 80 + c4 * 2);
            *(uint2*)(buf + F_B_H + off) = hi;
            *(uint2*)(buf + F_B_L + off) = lo;
        }
    }
}

__global__ __launch_bounds__(256, 1) void fc_mma_kernel(
    const float* __restrict__ fcw, const float* __restrict__ fcb,
    float* __restrict__ out)
{
    extern __shared__ char sm[];
    uint32_t sb = smem_u32(sm);
    int t = threadIdx.x, lane = t & 31, wid = t >> 5;
    int warp_m = wid & 3, warp_n = wid >> 2;
    int n0 = blockIdx.x * 128;
    int nt = warp_n ? 6 : 7;
    int t8base = warp_n ? 7 : 0;

    float acc[2][7][4];
    #pragma unroll
    for (int a = 0; a < 2; ++a)
        #pragma unroll
        for (int b = 0; b < 7; ++b)
            #pragma unroll
            for (int c = 0; c < 4; ++c) acc[a][b][c] = 0.f;

    int alr = ((lane >> 3) & 1) * 8 + (lane & 7);
    int alk = ((lane >> 4) & 1) * 8;
    uint32_t aoff = (uint32_t)((warp_m * 32 + alr) * 80 + alk * 2);
    int l2 = lane & 15;
    uint32_t boff = (uint32_t)((t8base * 8 + (l2 & 7)) * 80 + ((l2 >> 3) * 8) * 2);

    float4 pa[4], pb[4];
    fc_load(pa, pb, t, n0, 0, fcw);
    fc_store(sm, pa, pb, t);
    __syncthreads();

    for (int kc = 0; kc < 8; ++kc) {
        uint32_t sbc = sb + (uint32_t)((kc & 1) * FB_STRIDE);
        char* nxt = sm + ((kc & 1) ^ 1) * FB_STRIDE;
        if (kc < 7) fc_load(pa, pb, t, n0, (kc + 1) * 32, fcw);

        #pragma unroll
        for (int ks = 0; ks < 2; ++ks) {
            uint32_t aH[2][4], aL[2][4];
            #pragma unroll
            for (int mt = 0; mt < 2; ++mt) {
                uint32_t o = aoff + (uint32_t)(mt * 1280 + ks * 32);
                ldsm4(aH[mt], sbc + F_A_H + o);
                ldsm4(aL[mt], sbc + F_A_L + o);
            }
            #pragma unroll
            for (int t8 = 0; t8 < 7; ++t8) {
                if (t8 < nt) {
                    uint32_t bh[2], bl[2];
                    uint32_t o = boff + (uint32_t)(t8 * 640 + ks * 32);
                    ldsm2(bh, sbc + F_B_H + o);
                    ldsm2(bl, sbc + F_B_L + o);
                    #pragma unroll
                    for (int mt = 0; mt < 2; ++mt) {
                        mma16816(acc[mt][t8], aH[mt], bh);
                        mma16816(acc[mt][t8], aH[mt], bl);
                        mma16816(acc[mt][t8], aL[mt], bh);
                    }
                }
            }
        }
        if (kc < 7) fc_store(nxt, pa, pb, t);
        __syncthreads();
    }

    // epilogue
    int lane4 = lane >> 2, lc = lane & 3;
    for (int t8 = 0; t8 < nt; ++t8) {
        int col = (t8base + t8) * 8 + lc * 2;
        float2 bv = *(const float2*)&fcb[col];
        #pragma unroll
        for (int mt = 0; mt < 2; ++mt) {
            #pragma unroll
            for (int rs = 0; rs < 2; ++rs) {
                int m = n0 + warp_m * 32 + mt * 16 + rs * 8 + lane4;
                if (m < N_DST) {
                    float2 o = make_float2(acc[mt][t8][rs * 2 + 0] + bv.x,
                                           acc[mt][t8][rs * 2 + 1] + bv.y);
                    *(float2*)&out[(size_t)m * N_CLS + col] = o;
                }
            }
        }
    }
}

// ---------------------------------------------------------------------------
extern "C" void kernel_launch(void* const* d_in, const int* in_sizes, int n_in,
                              void* d_out, int out_size)
{
    const int*   tokens  = (const int*)  d_in[0];
    const int*   degrees = (const int*)  d_in[1];
    const float* emb     = (const float*)d_in[2];
    const float* W_ih    = (const float*)d_in[3];
    const float* W_hh    = (const float*)d_in[4];
    const float* b_ih    = (const float*)d_in[5];
    const float* b_hh    = (const float*)d_in[6];
    const float* gamma   = (const float*)d_in[7];
    const float* beta    = (const float*)d_in[8];
    const float* fc_w    = (const float*)d_in[9];
    const float* fc_b    = (const float*)d_in[10];
    float* out = (float*)d_out;

    cudaFuncSetAttribute(gru_mma_kernel, cudaFuncAttributeMaxDynamicSharedMemorySize, G_SMEM);
    cudaFuncSetAttribute(fc_mma_kernel,  cudaFuncAttributeMaxDynamicSharedMemorySize, F_SMEM);

    gather_kernel<<<(N_DST + 7) / 8, 256>>>(tokens, degrees, emb);
    gru_mma_kernel<<<dim3(8, 391), 256, G_SMEM>>>(W_ih, W_hh, b_ih, b_hh);
    ln_kernel<<<(N_DST + 7) / 8, 256>>>(degrees, gamma, beta);
    fc_mma_kernel<<<391, 256, F_SMEM>>>(fc_w, fc_b, out);
}